// round 8
// baseline (speedup 1.0000x reference)
#include <cuda_runtime.h>
#include <cstdint>

// VectorQuantizer: x[32,64,64,64] NCHW, codebook W[512,64].
// Per token (b,h,w): argmin_k ||x - W_k||^2, output W_k in NCHW.
// Strategy: fp32x2 packed FMA (FFMA2) distance kernel, W staged in smem,
// fused argmin + NCHW gather epilogue. One token per thread.

#define K_CB   512
#define D_DIM  64
#define HWSZ   4096          // 64*64 per image
#define THREADS 256
#define SMEM_BYTES ((K_CB * D_DIM + K_CB) * 4)   // 133120 B

#define FMA2(d, a, b, c) \
    asm("fma.rn.f32x2 %0, %1, %2, %3;" : "=l"(d) : "l"(a), "l"(b), "l"(c))
#define ADD2(d, a, b) \
    asm("add.rn.f32x2 %0, %1, %2;" : "=l"(d) : "l"(a), "l"(b))
#define PACK2(d, lo, hi) \
    asm("mov.b64 %0, {%1, %2};" : "=l"(d) : "r"(lo), "r"(hi))
#define UNPACK2(lo, hi, s) \
    asm("mov.b64 {%0, %1}, %2;" : "=r"(lo), "=r"(hi) : "l"(s))

__global__ __launch_bounds__(THREADS)
void vq_kernel(const float* __restrict__ x,
               const float* __restrict__ Wc,
               float* __restrict__ out)
{
    extern __shared__ float smem[];
    float* ws = smem;                       // [512][64] codebook
    float* wn = smem + K_CB * D_DIM;        // [512] row norms ||w_k||^2

    const int t  = threadIdx.x;
    const int b  = blockIdx.x >> 4;                 // 16 CTAs per image
    const int hw = ((blockIdx.x & 15) << 8) | t;    // token position in image

    // ---- Stage W into shared (coalesced, conflict-free STS.128) ----
    {
        const float4* Wg  = reinterpret_cast<const float4*>(Wc);
        float4*       wsv = reinterpret_cast<float4*>(ws);
        #pragma unroll
        for (int i = 0; i < 32; ++i)
            wsv[t + THREADS * i] = Wg[t + THREADS * i];

        // Row norms: thread t owns rows 2t, 2t+1; read from global (L2-hot).
        float s0 = 0.f, s1 = 0.f;
        #pragma unroll
        for (int i = 0; i < 32; ++i) {
            float4 v = __ldg(Wg + t * 32 + i);
            float ss = v.x * v.x + v.y * v.y + v.z * v.z + v.w * v.w;
            if (i < 16) s0 += ss; else s1 += ss;
        }
        wn[2 * t]     = s0;
        wn[2 * t + 1] = s1;
    }

    // ---- Load this token's feature vector (coalesced across threads),
    //      packed into 32 f32x2 registers; also ||x||^2 (kept so our
    //      distance rounds on the same fp32 grid as the reference) ----
    const float* xb = x + ((size_t)b * D_DIM) * HWSZ + hw;
    unsigned long long px[32];
    float xn = 0.f;
    #pragma unroll
    for (int i = 0; i < 32; ++i) {
        float f0 = __ldg(xb + (2 * i    ) * HWSZ);
        float f1 = __ldg(xb + (2 * i + 1) * HWSZ);
        xn += f0 * f0 + f1 * f1;
        PACK2(px[i], __float_as_uint(f0), __float_as_uint(f1));
    }

    __syncthreads();

    // ---- Main loop: dist_k = (xn + ||w_k||^2) - 2*<x,w_k>, rounded in the
    //      same order as the reference expression tree ----
    const ulonglong2* wsv2 = reinterpret_cast<const ulonglong2*>(ws);

    float best  = 3.4e38f;
    int   besti = 0;

    #pragma unroll 2
    for (int k = 0; k < K_CB; ++k) {
        // 4 independent f32x2 accumulator chains (8 fp32 partials)
        unsigned long long a0 = 0ull, a1 = 0ull, a2 = 0ull, a3 = 0ull;
        #pragma unroll
        for (int j = 0; j < 16; ++j) {
            ulonglong2 w = wsv2[k * 16 + j];   // LDS.128, warp-broadcast
            if ((j & 1) == 0) {
                FMA2(a0, px[2 * j    ], w.x, a0);
                FMA2(a1, px[2 * j + 1], w.y, a1);
            } else {
                FMA2(a2, px[2 * j    ], w.x, a2);
                FMA2(a3, px[2 * j + 1], w.y, a3);
            }
        }
        ADD2(a0, a0, a2);
        ADD2(a1, a1, a3);
        ADD2(a0, a0, a1);
        unsigned int lo, hi;
        UNPACK2(lo, hi, a0);
        float dot  = __uint_as_float(lo) + __uint_as_float(hi);
        float dist = (xn + wn[k]) - 2.0f * dot;        // match ref rounding order
        if (dist < best) { best = dist; besti = k; }   // strict < == first-min (jnp.argmin)
    }

    // ---- Gather winning codebook row (from global; L2-resident, avoids
    //      row-strided smem bank conflicts) and write NCHW coalesced ----
    const float4* wrow = reinterpret_cast<const float4*>(Wc + besti * D_DIM);
    float* ob = out + ((size_t)b * D_DIM) * HWSZ + hw;
    #pragma unroll
    for (int i = 0; i < 16; ++i) {
        float4 v = __ldg(wrow + i);
        ob[(4 * i    ) * HWSZ] = v.x;
        ob[(4 * i + 1) * HWSZ] = v.y;
        ob[(4 * i + 2) * HWSZ] = v.z;
        ob[(4 * i + 3) * HWSZ] = v.w;
    }
}

extern "C" void kernel_launch(void* const* d_in, const int* in_sizes, int n_in,
                              void* d_out, int out_size)
{
    const float* x = (const float*)d_in[0];
    const float* W = (const float*)d_in[1];
    // Defensive: identify codebook by element count (512*64 = 32768).
    if (n_in >= 2 && in_sizes[0] == K_CB * D_DIM) {
        x = (const float*)d_in[1];
        W = (const float*)d_in[0];
    }

    cudaFuncSetAttribute(vq_kernel,
                         cudaFuncAttributeMaxDynamicSharedMemorySize,
                         SMEM_BYTES);

    // 32 images * 16 CTAs/image = 512 CTAs, 256 tokens each.
    vq_kernel<<<512, THREADS, SMEM_BYTES>>>(x, W, (float*)d_out);
}

// round 16
// speedup vs baseline: 1.3781x; 1.3781x over previous
#include <cuda_runtime.h>
#include <cstdint>

// VectorQuantizer: x[32,64,64,64] NCHW, codebook W[512,64].
// v2: 2 tokens per thread — each smem w-load (LDS.128) feeds 4 FFMA2
// (two tokens), halving LDS wavefronts per FMA. smem holds -2*W so the
// dot chain directly accumulates -2<x,w> (exact scaling, bit-identical
// distances to the verified v1). 256 CTAs x 256 threads, 512 tokens/CTA.

#define K_CB   512
#define D_DIM  64
#define HWSZ   4096
#define THREADS 256
#define SMEM_BYTES ((K_CB * D_DIM + K_CB) * 4)   // 133120 B

#define FMA2(d, a, b, c) \
    asm("fma.rn.f32x2 %0, %1, %2, %3;" : "=l"(d) : "l"(a), "l"(b), "l"(c))
#define ADD2(d, a, b) \
    asm("add.rn.f32x2 %0, %1, %2;" : "=l"(d) : "l"(a), "l"(b))
#define PACK2(d, lo, hi) \
    asm("mov.b64 %0, {%1, %2};" : "=l"(d) : "r"(lo), "r"(hi))
#define UNPACK2(lo, hi, s) \
    asm("mov.b64 {%0, %1}, %2;" : "=r"(lo), "=r"(hi) : "l"(s))

__global__ __launch_bounds__(THREADS)
void vq_kernel(const float* __restrict__ x,
               const float* __restrict__ Wc,
               float* __restrict__ out)
{
    extern __shared__ float smem[];
    float* ws = smem;                       // [512][64] = -2 * codebook
    float* wn = smem + K_CB * D_DIM;        // [512] row norms ||w_k||^2

    const int t    = threadIdx.x;
    const int b    = blockIdx.x >> 3;              // 8 CTAs per image
    const int tok0 = ((blockIdx.x & 7) << 9) | t;  // first token; second = tok0+256

    // ---- Stage -2*W into shared (coalesced) + row norms ----
    {
        const float4* Wg  = reinterpret_cast<const float4*>(Wc);
        float4*       wsv = reinterpret_cast<float4*>(ws);
        #pragma unroll
        for (int i = 0; i < 32; ++i) {
            float4 v = Wg[t + THREADS * i];
            wsv[t + THREADS * i] =
                make_float4(-2.f * v.x, -2.f * v.y, -2.f * v.z, -2.f * v.w);
        }
        float s0 = 0.f, s1 = 0.f;
        #pragma unroll
        for (int i = 0; i < 32; ++i) {
            float4 v = __ldg(Wg + t * 32 + i);
            float ss = v.x * v.x + v.y * v.y + v.z * v.z + v.w * v.w;
            if (i < 16) s0 += ss; else s1 += ss;
        }
        wn[2 * t]     = s0;
        wn[2 * t + 1] = s1;
    }

    // ---- Load two tokens' features into packed f32x2 registers ----
    const float* xbA = x + ((size_t)b * D_DIM) * HWSZ + tok0;
    const float* xbB = xbA + 256;
    unsigned long long pxA[32], pxB[32];
    float xnA = 0.f, xnB = 0.f;
    #pragma unroll
    for (int i = 0; i < 32; ++i) {
        float a0 = __ldg(xbA + (2 * i    ) * HWSZ);
        float a1 = __ldg(xbA + (2 * i + 1) * HWSZ);
        xnA += a0 * a0 + a1 * a1;
        PACK2(pxA[i], __float_as_uint(a0), __float_as_uint(a1));
        float b0 = __ldg(xbB + (2 * i    ) * HWSZ);
        float b1 = __ldg(xbB + (2 * i + 1) * HWSZ);
        xnB += b0 * b0 + b1 * b1;
        PACK2(pxB[i], __float_as_uint(b0), __float_as_uint(b1));
    }

    __syncthreads();

    // ---- Main loop: one w-load feeds both tokens (4 FMA2 / LDS.128) ----
    const ulonglong2* wsv2 = reinterpret_cast<const ulonglong2*>(ws);

    float bestA = 3.4e38f, bestB = 3.4e38f;
    int   idxA  = 0,       idxB  = 0;

    for (int k = 0; k < K_CB; ++k) {
        unsigned long long a0 = 0ull, a1 = 0ull, a2 = 0ull, a3 = 0ull;
        unsigned long long c0 = 0ull, c1 = 0ull, c2 = 0ull, c3 = 0ull;
        #pragma unroll
        for (int j = 0; j < 16; ++j) {
            ulonglong2 w = wsv2[k * 16 + j];   // LDS.128, warp-broadcast
            if ((j & 1) == 0) {
                FMA2(a0, pxA[2 * j    ], w.x, a0);
                FMA2(c0, pxB[2 * j    ], w.x, c0);
                FMA2(a1, pxA[2 * j + 1], w.y, a1);
                FMA2(c1, pxB[2 * j + 1], w.y, c1);
            } else {
                FMA2(a2, pxA[2 * j    ], w.x, a2);
                FMA2(c2, pxB[2 * j    ], w.x, c2);
                FMA2(a3, pxA[2 * j + 1], w.y, a3);
                FMA2(c3, pxB[2 * j + 1], w.y, c3);
            }
        }
        ADD2(a0, a0, a2); ADD2(a1, a1, a3); ADD2(a0, a0, a1);
        ADD2(c0, c0, c2); ADD2(c1, c1, c3); ADD2(c0, c0, c1);
        unsigned int lo, hi;
        UNPACK2(lo, hi, a0);
        float sA = __uint_as_float(lo) + __uint_as_float(hi);   // == -2*dotA exactly
        UNPACK2(lo, hi, c0);
        float sB = __uint_as_float(lo) + __uint_as_float(hi);
        float wk = wn[k];
        float dA = (xnA + wk) + sA;   // same rounding grid as verified v1
        float dB = (xnB + wk) + sB;
        if (dA < bestA) { bestA = dA; idxA = k; }
        if (dB < bestB) { bestB = dB; idxB = k; }
    }

    // ---- Gather winning rows and write NCHW coalesced ----
    const float4* wrA = reinterpret_cast<const float4*>(Wc + idxA * D_DIM);
    const float4* wrB = reinterpret_cast<const float4*>(Wc + idxB * D_DIM);
    float* obA = out + ((size_t)b * D_DIM) * HWSZ + tok0;
    float* obB = obA + 256;
    #pragma unroll
    for (int i = 0; i < 16; ++i) {
        float4 v = __ldg(wrA + i);
        obA[(4 * i    ) * HWSZ] = v.x;
        obA[(4 * i + 1) * HWSZ] = v.y;
        obA[(4 * i + 2) * HWSZ] = v.z;
        obA[(4 * i + 3) * HWSZ] = v.w;
        float4 u = __ldg(wrB + i);
        obB[(4 * i    ) * HWSZ] = u.x;
        obB[(4 * i + 1) * HWSZ] = u.y;
        obB[(4 * i + 2) * HWSZ] = u.z;
        obB[(4 * i + 3) * HWSZ] = u.w;
    }
}

extern "C" void kernel_launch(void* const* d_in, const int* in_sizes, int n_in,
                              void* d_out, int out_size)
{
    const float* x = (const float*)d_in[0];
    const float* W = (const float*)d_in[1];
    if (n_in >= 2 && in_sizes[0] == K_CB * D_DIM) {
        x = (const float*)d_in[1];
        W = (const float*)d_in[0];
    }

    cudaFuncSetAttribute(vq_kernel,
                         cudaFuncAttributeMaxDynamicSharedMemorySize,
                         SMEM_BYTES);

    // 32 images * 8 CTAs/image = 256 CTAs, 512 tokens each (2/thread).
    vq_kernel<<<256, THREADS, SMEM_BYTES>>>(x, W, (float*)d_out);
}